// round 14
// baseline (speedup 1.0000x reference)
#include <cuda_runtime.h>

// GraphAttentionHeadModule: N=8192, IN_F=256, OUT_F=64, alpha=0.2
// out = elu( softmax(mask(leaky_relu(s1 + s2^T))) @ (X@W) )

#define GN 8192
#define GIN 256
#define GOUT 64
#define CAPV 20.0f
#define JT 64

__device__ float g_h[GN * GOUT];   // h_prime, 2 MB
__device__ float g_s1[GN];
__device__ float g_s2[GN];

// ---------------------------------------------------------------------------
// Kernel 1: h = X @ W.  grid 1024, block 256, 8 rows/block (occupancy fix).
// c = t&63 channel; rg = t>>6 -> 2 rows each. X row loads are warp-broadcast.
// ---------------------------------------------------------------------------
__global__ void __launch_bounds__(256) gat_hprime_kernel(
    const float* __restrict__ X, const float* __restrict__ W)
{
    const int t = threadIdx.x;
    const int c = t & 63;
    const int rg = t >> 6;                 // 0..3
    const int r0 = blockIdx.x * 8 + rg * 2;

    float a0 = 0.f, a1 = 0.f;
#pragma unroll 4
    for (int k = 0; k < GIN; k += 4) {
        const float w0 = W[(k + 0) * GOUT + c];
        const float w1 = W[(k + 1) * GOUT + c];
        const float w2 = W[(k + 2) * GOUT + c];
        const float w3 = W[(k + 3) * GOUT + c];
        const float4 x0 = *(const float4*)(X + (size_t)r0 * GIN + k);
        const float4 x1 = *(const float4*)(X + (size_t)(r0 + 1) * GIN + k);
        a0 += x0.x * w0 + x0.y * w1 + x0.z * w2 + x0.w * w3;
        a1 += x1.x * w0 + x1.y * w1 + x1.z * w2 + x1.w * w3;
    }
    g_h[(size_t)r0 * GOUT + c]       = a0;
    g_h[(size_t)(r0 + 1) * GOUT + c] = a1;
}

// ---------------------------------------------------------------------------
// Kernel 2: s1 = h @ a1, s2 = h @ a2.  warp per row (strided).
// ---------------------------------------------------------------------------
__global__ void __launch_bounds__(256) gat_scores_kernel(
    const float* __restrict__ a1, const float* __restrict__ a2)
{
    const int lane = threadIdx.x & 31;
    const int gwid = (blockIdx.x * blockDim.x + threadIdx.x) >> 5;  // 0..2047

    const float2 a1v = *(const float2*)(a1 + lane * 2);
    const float2 a2v = *(const float2*)(a2 + lane * 2);

    for (int r = gwid; r < GN; r += 2048) {
        const float2 hv = *(const float2*)(g_h + (size_t)r * GOUT + lane * 2);
        float p1 = hv.x * a1v.x + hv.y * a1v.y;
        float p2 = hv.x * a2v.x + hv.y * a2v.y;
#pragma unroll
        for (int off = 16; off > 0; off >>= 1) {
            p1 += __shfl_xor_sync(0xffffffffu, p1, off);
            p2 += __shfl_xor_sync(0xffffffffu, p2, off);
        }
        if (lane == 0) { g_s1[r] = p1; g_s2[r] = p2; }
    }
}

// ---------------------------------------------------------------------------
// Kernel 3 v2: fused masked-softmax weighted sum + ELU.
// grid 256 (32 rows/block), block 256, 2 blocks/SM.
// Per 64-j tile:
//  phase 1: thread (r=t&31, jg=t>>5) computes 8 weights for row r, stores
//           TRANSPOSED w_s[r][j] (padded 68 for alignment+banks); also stages
//           h tile h_s[64][64] via coalesced float4 copy.
//  phase 2: thread (r=t>>3, c0=(t&7)*8) owns out[row r][c0..c0+7] fully:
//           4 f32x2 accumulators only (8 regs) -> no spills, no cross-warp
//           epilogue reduction. fma.rn.f32x2 on smem-resident operands.
// ---------------------------------------------------------------------------
__device__ __forceinline__ void fma2(unsigned long long& a,
                                     unsigned long long b,
                                     unsigned long long c)
{
    asm("fma.rn.f32x2 %0, %1, %2, %0;" : "+l"(a) : "l"(b), "l"(c));
}

__global__ void __launch_bounds__(256, 2) gat_attn_kernel(
    const int* __restrict__ adj, float* __restrict__ out)
{
    __shared__ float s1s[32];
    __shared__ float denomS[32];
    __shared__ float dred[256];
    __shared__ __align__(16) float w_s[32][68];    // 8704 B, [row][j] padded
    __shared__ __align__(16) float h_s[JT][GOUT];  // 16 KB

    const int t    = threadIdx.x;
    const int row0 = blockIdx.x * 32;
    const int r1   = t & 31;          // phase-1 row
    const int jg   = t >> 5;          // 0..7 j-group
    const int r2   = t >> 3;          // phase-2 row
    const int c0   = (t & 7) * 8;     // phase-2 channel base

    if (t < 32) s1s[t] = g_s1[row0 + t];
    __syncthreads();
    const float s1r = s1s[r1];
    const int* adjrow = adj + (size_t)(row0 + r1) * GN;

    unsigned long long acc01 = 0ULL, acc23 = 0ULL, acc45 = 0ULL, acc67 = 0ULL;
    float dn = 0.f;

    for (int j0 = 0; j0 < GN; j0 += JT) {
        // ---- phase 1: weights (transposed) ----
        {
            const int j = j0 + jg * 8;
            const int4   a4a = *(const int4*)(adjrow + j);
            const int4   a4b = *(const int4*)(adjrow + j + 4);
            const float4 s2a = *(const float4*)(g_s2 + j);
            const float4 s2b = *(const float4*)(g_s2 + j + 4);

            float e, l, w0, w1, w2, w3, w4, w5, w6, w7;
            e = s1r + s2a.x; l = fmaxf(e, 0.2f * e) - CAPV; w0 = (a4a.x > 0) ? __expf(l) : 0.f;
            e = s1r + s2a.y; l = fmaxf(e, 0.2f * e) - CAPV; w1 = (a4a.y > 0) ? __expf(l) : 0.f;
            e = s1r + s2a.z; l = fmaxf(e, 0.2f * e) - CAPV; w2 = (a4a.z > 0) ? __expf(l) : 0.f;
            e = s1r + s2a.w; l = fmaxf(e, 0.2f * e) - CAPV; w3 = (a4a.w > 0) ? __expf(l) : 0.f;
            e = s1r + s2b.x; l = fmaxf(e, 0.2f * e) - CAPV; w4 = (a4b.x > 0) ? __expf(l) : 0.f;
            e = s1r + s2b.y; l = fmaxf(e, 0.2f * e) - CAPV; w5 = (a4b.y > 0) ? __expf(l) : 0.f;
            e = s1r + s2b.z; l = fmaxf(e, 0.2f * e) - CAPV; w6 = (a4b.z > 0) ? __expf(l) : 0.f;
            e = s1r + s2b.w; l = fmaxf(e, 0.2f * e) - CAPV; w7 = (a4b.w > 0) ? __expf(l) : 0.f;

            dn += ((w0 + w1) + (w2 + w3)) + ((w4 + w5) + (w6 + w7));

            float4* wp0 = (float4*)&w_s[r1][jg * 8];
            wp0[0] = make_float4(w0, w1, w2, w3);
            wp0[1] = make_float4(w4, w5, w6, w7);
        }

        // ---- phase 1b: stage h tile (coalesced) ----
#pragma unroll
        for (int i = 0; i < 4; ++i) {
            const int f = t + 256 * i;            // float4 index, 0..1023
            const float4 hv = *(const float4*)(g_h +
                    (size_t)(j0 + (f >> 4)) * GOUT + (f & 15) * 4);
            *(float4*)&h_s[f >> 4][(f & 15) * 4] = hv;
        }
        __syncthreads();

        // ---- phase 2: accumulate 8 channels of one row ----
#pragma unroll 4
        for (int jj = 0; jj < JT; jj += 4) {
            const float4 wv = *(const float4*)&w_s[r2][jj];
#pragma unroll
            for (int dj = 0; dj < 4; ++dj) {
                const float w = (dj == 0) ? wv.x : (dj == 1) ? wv.y
                              : (dj == 2) ? wv.z : wv.w;
                unsigned long long wp;
                asm("mov.b64 %0, {%1, %1};" : "=l"(wp) : "f"(w));
                const ulonglong2 ha = *(const ulonglong2*)&h_s[jj + dj][c0];
                const ulonglong2 hb = *(const ulonglong2*)&h_s[jj + dj][c0 + 4];
                fma2(acc01, wp, ha.x);
                fma2(acc23, wp, ha.y);
                fma2(acc45, wp, hb.x);
                fma2(acc67, wp, hb.y);
            }
        }
        __syncthreads();
    }

    // ---- denominator reduction (deterministic) ----
    dred[t] = dn;
    __syncthreads();
    if (t < 32) {
        float s = 0.f;
#pragma unroll
        for (int q = 0; q < 8; ++q) s += dred[t + 32 * q];
        denomS[t] = s;
    }
    __syncthreads();

    // ---- epilogue: thread owns out[row0+r2][c0..c0+7] entirely ----
    const float inv = 1.f / denomS[r2];
    float o[8];
    o[0] = __uint_as_float((unsigned)(acc01 & 0xffffffffu));
    o[1] = __uint_as_float((unsigned)(acc01 >> 32));
    o[2] = __uint_as_float((unsigned)(acc23 & 0xffffffffu));
    o[3] = __uint_as_float((unsigned)(acc23 >> 32));
    o[4] = __uint_as_float((unsigned)(acc45 & 0xffffffffu));
    o[5] = __uint_as_float((unsigned)(acc45 >> 32));
    o[6] = __uint_as_float((unsigned)(acc67 & 0xffffffffu));
    o[7] = __uint_as_float((unsigned)(acc67 >> 32));

#pragma unroll
    for (int i = 0; i < 8; ++i) {
        float v = o[i] * inv;
        o[i] = (v > 0.f) ? v : expm1f(v);          // ELU
    }
    float4* op = (float4*)(out + (size_t)(row0 + r2) * GOUT + c0);
    op[0] = make_float4(o[0], o[1], o[2], o[3]);
    op[1] = make_float4(o[4], o[5], o[6], o[7]);
}

// ---------------------------------------------------------------------------
extern "C" void kernel_launch(void* const* d_in, const int* in_sizes, int n_in,
                              void* d_out, int out_size)
{
    const float* X   = (const float*)d_in[0];
    const int*   adj = (const int*)d_in[1];
    const float* W   = (const float*)d_in[2];
    const float* a1  = (const float*)d_in[3];
    const float* a2  = (const float*)d_in[4];
    float* out = (float*)d_out;

    gat_hprime_kernel<<<1024, 256>>>(X, W);
    gat_scores_kernel<<<256, 256>>>(a1, a2);
    gat_attn_kernel<<<256, 256>>>(adj, out);
}

// round 15
// speedup vs baseline: 4.0406x; 4.0406x over previous
#include <cuda_runtime.h>

// GraphAttentionHeadModule: N=8192, IN_F=256, OUT_F=64, alpha=0.2
// out = elu( softmax(mask(leaky_relu(s1 + s2^T))) @ (X@W) )

#define GN 8192
#define GIN 256
#define GOUT 64
#define CAPV 20.0f
#define JT 64

__device__ float g_h[GN * GOUT];   // h_prime, 2 MB
__device__ float g_s1[GN];
__device__ float g_s2[GN];

// ---------------------------------------------------------------------------
// Kernel 1: h = X @ W.  grid 1024, block 256, 8 rows/block. (48->30us in R14)
// ---------------------------------------------------------------------------
__global__ void __launch_bounds__(256) gat_hprime_kernel(
    const float* __restrict__ X, const float* __restrict__ W)
{
    const int t = threadIdx.x;
    const int c = t & 63;
    const int rg = t >> 6;                 // 0..3
    const int r0 = blockIdx.x * 8 + rg * 2;

    float a0 = 0.f, a1 = 0.f;
#pragma unroll 4
    for (int k = 0; k < GIN; k += 4) {
        const float w0 = W[(k + 0) * GOUT + c];
        const float w1 = W[(k + 1) * GOUT + c];
        const float w2 = W[(k + 2) * GOUT + c];
        const float w3 = W[(k + 3) * GOUT + c];
        const float4 x0 = *(const float4*)(X + (size_t)r0 * GIN + k);
        const float4 x1 = *(const float4*)(X + (size_t)(r0 + 1) * GIN + k);
        a0 += x0.x * w0 + x0.y * w1 + x0.z * w2 + x0.w * w3;
        a1 += x1.x * w0 + x1.y * w1 + x1.z * w2 + x1.w * w3;
    }
    g_h[(size_t)r0 * GOUT + c]       = a0;
    g_h[(size_t)(r0 + 1) * GOUT + c] = a1;
}

// ---------------------------------------------------------------------------
// Kernel 2: s1 = h @ a1, s2 = h @ a2.
// ---------------------------------------------------------------------------
__global__ void __launch_bounds__(256) gat_scores_kernel(
    const float* __restrict__ a1, const float* __restrict__ a2)
{
    const int lane = threadIdx.x & 31;
    const int gwid = (blockIdx.x * blockDim.x + threadIdx.x) >> 5;

    const float2 a1v = *(const float2*)(a1 + lane * 2);
    const float2 a2v = *(const float2*)(a2 + lane * 2);

    for (int r = gwid; r < GN; r += 2048) {
        const float2 hv = *(const float2*)(g_h + (size_t)r * GOUT + lane * 2);
        float p1 = hv.x * a1v.x + hv.y * a1v.y;
        float p2 = hv.x * a2v.x + hv.y * a2v.y;
#pragma unroll
        for (int off = 16; off > 0; off >>= 1) {
            p1 += __shfl_xor_sync(0xffffffffu, p1, off);
            p2 += __shfl_xor_sync(0xffffffffu, p2, off);
        }
        if (lane == 0) { g_s1[r] = p1; g_s2[r] = p2; }
    }
}

// ---------------------------------------------------------------------------
// Kernel 3 v4: tf32 tensor-core fused masked-softmax @ h + ELU.
// grid 256 (32 rows/block), block 256 (8 warps), 2 blocks/SM, single wave.
// Per 64-j tile:
//   phase 1: thread (r1=t&31, jg=t>>5) computes 8 weights (fp32 exp, fixed
//            -20 shift), accumulates fp32 denom, stores tf32-rounded bits to
//            w_s[32][68] (conflict-free per 8-lane phase). Stages h tile to
//            h_s[64][72] with tf32 rounding (stride 72 => B-frag lds
//            conflict-free).
//   phase 2: warp w: m=w&1 (16 rows), nq=w>>1 (16 ch). 8 ksteps x 2 ntiles
//            mma.sync.m16n8k8.tf32, C in 8 f32 regs. Fragment loads are
//            plain LDS.32, all bank-conflict-free by layout construction.
// Epilogue: fp32 denom reduction, divide, ELU, direct float2 stores.
// ---------------------------------------------------------------------------
__device__ __forceinline__ unsigned tf32r(float f) {
    unsigned u;
    asm("cvt.rna.tf32.f32 %0, %1;" : "=r"(u) : "f"(f));
    return u;
}

__device__ __forceinline__ void mma_tf32(
    float& d0, float& d1, float& d2, float& d3,
    unsigned a0, unsigned a1, unsigned a2, unsigned a3,
    unsigned b0, unsigned b1)
{
    asm("mma.sync.aligned.m16n8k8.row.col.f32.tf32.tf32.f32 "
        "{%0,%1,%2,%3},{%4,%5,%6,%7},{%8,%9},{%0,%1,%2,%3};"
        : "+f"(d0), "+f"(d1), "+f"(d2), "+f"(d3)
        : "r"(a0), "r"(a1), "r"(a2), "r"(a3), "r"(b0), "r"(b1));
}

__global__ void __launch_bounds__(256, 2) gat_attn_kernel(
    const int* __restrict__ adj, float* __restrict__ out)
{
    __shared__ float s1s[32];
    __shared__ float denomS[32];
    __shared__ float dred[256];
    __shared__ __align__(16) float w_s[32][68];   // P tile, tf32 bits
    __shared__ __align__(16) float h_s[64][72];   // H tile, tf32 bits

    const int t    = threadIdx.x;
    const int lane = t & 31;
    const int w    = t >> 5;
    const int row0 = blockIdx.x * 32;

    // phase-1 ids
    const int r1 = t & 31;
    const int jg = t >> 5;            // 0..7, 8 j each
    // phase-2 ids
    const int m   = w & 1;            // M-tile (16 rows)
    const int nq  = w >> 1;           // 0..3, 16-ch slice
    const int gid = lane >> 2;        // 0..7
    const int tig = lane & 3;         // 0..3

    if (t < 32) s1s[t] = g_s1[row0 + t];
    __syncthreads();
    const float s1r = s1s[r1];
    const int* adjrow = adj + (size_t)(row0 + r1) * GN;

    // C fragments: [ntile][4]
    float c00 = 0.f, c01 = 0.f, c02 = 0.f, c03 = 0.f;
    float c10 = 0.f, c11 = 0.f, c12 = 0.f, c13 = 0.f;
    float dn = 0.f;

    for (int j0 = 0; j0 < GN; j0 += JT) {
        // ---- phase 1: weights (fp32 exp, tf32 store) ----
        {
            const int j = j0 + jg * 8;
            const int4   a4a = *(const int4*)(adjrow + j);
            const int4   a4b = *(const int4*)(adjrow + j + 4);
            const float4 s2a = *(const float4*)(g_s2 + j);
            const float4 s2b = *(const float4*)(g_s2 + j + 4);

            float e, l, w0, w1, w2, w3, w4, w5, w6, w7;
            e = s1r + s2a.x; l = fmaxf(e, 0.2f * e) - CAPV; w0 = (a4a.x > 0) ? __expf(l) : 0.f;
            e = s1r + s2a.y; l = fmaxf(e, 0.2f * e) - CAPV; w1 = (a4a.y > 0) ? __expf(l) : 0.f;
            e = s1r + s2a.z; l = fmaxf(e, 0.2f * e) - CAPV; w2 = (a4a.z > 0) ? __expf(l) : 0.f;
            e = s1r + s2a.w; l = fmaxf(e, 0.2f * e) - CAPV; w3 = (a4a.w > 0) ? __expf(l) : 0.f;
            e = s1r + s2b.x; l = fmaxf(e, 0.2f * e) - CAPV; w4 = (a4b.x > 0) ? __expf(l) : 0.f;
            e = s1r + s2b.y; l = fmaxf(e, 0.2f * e) - CAPV; w5 = (a4b.y > 0) ? __expf(l) : 0.f;
            e = s1r + s2b.z; l = fmaxf(e, 0.2f * e) - CAPV; w6 = (a4b.z > 0) ? __expf(l) : 0.f;
            e = s1r + s2b.w; l = fmaxf(e, 0.2f * e) - CAPV; w7 = (a4b.w > 0) ? __expf(l) : 0.f;

            dn += ((w0 + w1) + (w2 + w3)) + ((w4 + w5) + (w6 + w7));

            float4* wp = (float4*)&w_s[r1][jg * 8];
            wp[0] = make_float4(__uint_as_float(tf32r(w0)), __uint_as_float(tf32r(w1)),
                                __uint_as_float(tf32r(w2)), __uint_as_float(tf32r(w3)));
            wp[1] = make_float4(__uint_as_float(tf32r(w4)), __uint_as_float(tf32r(w5)),
                                __uint_as_float(tf32r(w6)), __uint_as_float(tf32r(w7)));
        }

        // ---- phase 1b: stage h tile (coalesced, tf32 rounding) ----
#pragma unroll
        for (int i = 0; i < 4; ++i) {
            const int f = t + 256 * i;            // float4 index 0..1023
            const float4 hv = *(const float4*)(g_h +
                    (size_t)(j0 + (f >> 4)) * GOUT + (f & 15) * 4);
            *(float4*)&h_s[f >> 4][(f & 15) * 4] = make_float4(
                __uint_as_float(tf32r(hv.x)), __uint_as_float(tf32r(hv.y)),
                __uint_as_float(tf32r(hv.z)), __uint_as_float(tf32r(hv.w)));
        }
        __syncthreads();

        // ---- phase 2: 8 ksteps x 2 ntiles of m16n8k8 tf32 ----
#pragma unroll
        for (int ks = 0; ks < 8; ++ks) {
            const unsigned a0 = __float_as_uint(w_s[m * 16 + gid][ks * 8 + tig]);
            const unsigned a1 = __float_as_uint(w_s[m * 16 + gid + 8][ks * 8 + tig]);
            const unsigned a2 = __float_as_uint(w_s[m * 16 + gid][ks * 8 + tig + 4]);
            const unsigned a3 = __float_as_uint(w_s[m * 16 + gid + 8][ks * 8 + tig + 4]);

            const unsigned b00 = __float_as_uint(h_s[ks * 8 + tig][nq * 16 + gid]);
            const unsigned b01 = __float_as_uint(h_s[ks * 8 + tig + 4][nq * 16 + gid]);
            mma_tf32(c00, c01, c02, c03, a0, a1, a2, a3, b00, b01);

            const unsigned b10 = __float_as_uint(h_s[ks * 8 + tig][nq * 16 + 8 + gid]);
            const unsigned b11 = __float_as_uint(h_s[ks * 8 + tig + 4][nq * 16 + 8 + gid]);
            mma_tf32(c10, c11, c12, c13, a0, a1, a2, a3, b10, b11);
        }
        __syncthreads();
    }

    // ---- denominator reduction (deterministic, fp32) ----
    dred[t] = dn;
    __syncthreads();
    if (t < 32) {
        float s = 0.f;
#pragma unroll
        for (int q = 0; q < 8; ++q) s += dred[q * 32 + t];
        denomS[t] = s;
    }
    __syncthreads();

    // ---- epilogue: divide, ELU, store ----
    const int r_lo = m * 16 + gid;
    const int r_hi = r_lo + 8;
    const float inv_lo = 1.f / denomS[r_lo];
    const float inv_hi = 1.f / denomS[r_hi];

    float v;
    float2 o;
    const int colA = nq * 16 + tig * 2;
    const int colB = colA + 8;

    v = c00 * inv_lo; o.x = (v > 0.f) ? v : expm1f(v);
    v = c01 * inv_lo; o.y = (v > 0.f) ? v : expm1f(v);
    *(float2*)(out + (size_t)(row0 + r_lo) * GOUT + colA) = o;
    v = c02 * inv_hi; o.x = (v > 0.f) ? v : expm1f(v);
    v = c03 * inv_hi; o.y = (v > 0.f) ? v : expm1f(v);
    *(float2*)(out + (size_t)(row0 + r_hi) * GOUT + colA) = o;
    v = c10 * inv_lo; o.x = (v > 0.f) ? v : expm1f(v);
    v = c11 * inv_lo; o.y = (v > 0.f) ? v : expm1f(v);
    *(float2*)(out + (size_t)(row0 + r_lo) * GOUT + colB) = o;
    v = c12 * inv_hi; o.x = (v > 0.f) ? v : expm1f(v);
    v = c13 * inv_hi; o.y = (v > 0.f) ? v : expm1f(v);
    *(float2*)(out + (size_t)(row0 + r_hi) * GOUT + colB) = o;
}

// ---------------------------------------------------------------------------
extern "C" void kernel_launch(void* const* d_in, const int* in_sizes, int n_in,
                              void* d_out, int out_size)
{
    const float* X   = (const float*)d_in[0];
    const int*   adj = (const int*)d_in[1];
    const float* W   = (const float*)d_in[2];
    const float* a1  = (const float*)d_in[3];
    const float* a2  = (const float*)d_in[4];
    float* out = (float*)d_out;

    gat_hprime_kernel<<<1024, 256>>>(X, W);
    gat_scores_kernel<<<256, 256>>>(a1, a2);
    gat_attn_kernel<<<256, 256>>>(adj, out);
}

// round 16
// speedup vs baseline: 4.5919x; 1.1364x over previous
#include <cuda_runtime.h>

// GraphAttentionHeadModule: N=8192, IN_F=256, OUT_F=64, alpha=0.2
// out = elu( softmax(mask(leaky_relu(s1 + s2^T))) @ (X@W) )

#define GN 8192
#define GIN 256
#define GOUT 64
#define CAPV 20.0f
#define JT 64

__device__ float g_h[GN * GOUT];   // h_prime, 2 MB
__device__ float g_s1[GN];
__device__ float g_s2[GN];

// ---------------------------------------------------------------------------
// Kernel 1: h = X @ W.  grid 1024, block 256, 8 rows/block.
// ---------------------------------------------------------------------------
__global__ void __launch_bounds__(256) gat_hprime_kernel(
    const float* __restrict__ X, const float* __restrict__ W)
{
    const int t = threadIdx.x;
    const int c = t & 63;
    const int rg = t >> 6;                 // 0..3
    const int r0 = blockIdx.x * 8 + rg * 2;

    float a0 = 0.f, a1 = 0.f;
#pragma unroll 4
    for (int k = 0; k < GIN; k += 4) {
        const float w0 = W[(k + 0) * GOUT + c];
        const float w1 = W[(k + 1) * GOUT + c];
        const float w2 = W[(k + 2) * GOUT + c];
        const float w3 = W[(k + 3) * GOUT + c];
        const float4 x0 = *(const float4*)(X + (size_t)r0 * GIN + k);
        const float4 x1 = *(const float4*)(X + (size_t)(r0 + 1) * GIN + k);
        a0 += x0.x * w0 + x0.y * w1 + x0.z * w2 + x0.w * w3;
        a1 += x1.x * w0 + x1.y * w1 + x1.z * w2 + x1.w * w3;
    }
    g_h[(size_t)r0 * GOUT + c]       = a0;
    g_h[(size_t)(r0 + 1) * GOUT + c] = a1;
}

// ---------------------------------------------------------------------------
// Kernel 2: s1 = h @ a1, s2 = h @ a2.
// ---------------------------------------------------------------------------
__global__ void __launch_bounds__(256) gat_scores_kernel(
    const float* __restrict__ a1, const float* __restrict__ a2)
{
    const int lane = threadIdx.x & 31;
    const int gwid = (blockIdx.x * blockDim.x + threadIdx.x) >> 5;

    const float2 a1v = *(const float2*)(a1 + lane * 2);
    const float2 a2v = *(const float2*)(a2 + lane * 2);

    for (int r = gwid; r < GN; r += 2048) {
        const float2 hv = *(const float2*)(g_h + (size_t)r * GOUT + lane * 2);
        float p1 = hv.x * a1v.x + hv.y * a1v.y;
        float p2 = hv.x * a2v.x + hv.y * a2v.y;
#pragma unroll
        for (int off = 16; off > 0; off >>= 1) {
            p1 += __shfl_xor_sync(0xffffffffu, p1, off);
            p2 += __shfl_xor_sync(0xffffffffu, p2, off);
        }
        if (lane == 0) { g_s1[r] = p1; g_s2[r] = p2; }
    }
}

// ---------------------------------------------------------------------------
// Kernel 3 v5: tf32 MMA + double-buffered smem + register prefetch.
// grid 256 (32 rows/block), block 256 (8 warps), 2 blocks/SM.
// Per tile: prefetch LDGs for tile t+1 -> 16 MMAs on buf[cur] -> exp+convert
// prefetched regs into buf[cur^1] -> one __syncthreads. DRAM latency hidden
// under MMA work; 1 barrier/tile instead of 2.
// ---------------------------------------------------------------------------
__device__ __forceinline__ unsigned tf32r(float f) {
    unsigned u;
    asm("cvt.rna.tf32.f32 %0, %1;" : "=r"(u) : "f"(f));
    return u;
}

__device__ __forceinline__ void mma_tf32(
    float& d0, float& d1, float& d2, float& d3,
    unsigned a0, unsigned a1, unsigned a2, unsigned a3,
    unsigned b0, unsigned b1)
{
    asm("mma.sync.aligned.m16n8k8.row.col.f32.tf32.tf32.f32 "
        "{%0,%1,%2,%3},{%4,%5,%6,%7},{%8,%9},{%0,%1,%2,%3};"
        : "+f"(d0), "+f"(d1), "+f"(d2), "+f"(d3)
        : "r"(a0), "r"(a1), "r"(a2), "r"(a3), "r"(b0), "r"(b1));
}

__global__ void __launch_bounds__(256, 2) gat_attn_kernel(
    const int* __restrict__ adj, float* __restrict__ out)
{
    __shared__ float s1s[32];
    __shared__ float denomS[32];
    __shared__ float dred[256];
    __shared__ __align__(16) float w_s[2][32][68];   // P tiles, tf32 bits
    __shared__ __align__(16) float h_s[2][64][72];   // H tiles, tf32 bits

    const int t    = threadIdx.x;
    const int lane = t & 31;
    const int w    = t >> 5;
    const int row0 = blockIdx.x * 32;

    // phase-1 ids
    const int r1 = t & 31;
    const int jg = t >> 5;            // 0..7, 8 j each
    // phase-2 ids
    const int m   = w & 1;            // M-tile (16 rows)
    const int nq  = w >> 1;           // 0..3, 16-ch slice
    const int gid = lane >> 2;        // 0..7
    const int tig = lane & 3;         // 0..3

    if (t < 32) s1s[t] = g_s1[row0 + t];
    __syncthreads();
    const float s1r = s1s[r1];
    const int* adjrow = adj + (size_t)(row0 + r1) * GN;

    float c00 = 0.f, c01 = 0.f, c02 = 0.f, c03 = 0.f;
    float c10 = 0.f, c11 = 0.f, c12 = 0.f, c13 = 0.f;
    float dn = 0.f;

    // ---- prologue: load + fill buffer 0 for tile 0 ----
    int4   pa0, pa1;
    float4 ps0, ps1;
    float4 ph0, ph1, ph2, ph3;
    {
        const int j = jg * 8;
        pa0 = *(const int4*)(adjrow + j);
        pa1 = *(const int4*)(adjrow + j + 4);
        ps0 = *(const float4*)(g_s2 + j);
        ps1 = *(const float4*)(g_s2 + j + 4);
        ph0 = *(const float4*)(g_h + (size_t)(t >> 4) * GOUT + (t & 15) * 4);
        ph1 = *(const float4*)(g_h + (size_t)((t + 256) >> 4) * GOUT + ((t + 256) & 15) * 4);
        ph2 = *(const float4*)(g_h + (size_t)((t + 512) >> 4) * GOUT + ((t + 512) & 15) * 4);
        ph3 = *(const float4*)(g_h + (size_t)((t + 768) >> 4) * GOUT + ((t + 768) & 15) * 4);
    }
#define FILL_BUF(buf)                                                          \
    do {                                                                       \
        float e, l, w0, w1, w2, w3, w4, w5, w6, w7;                            \
        e = s1r + ps0.x; l = fmaxf(e, 0.2f * e) - CAPV; w0 = (pa0.x > 0) ? __expf(l) : 0.f; \
        e = s1r + ps0.y; l = fmaxf(e, 0.2f * e) - CAPV; w1 = (pa0.y > 0) ? __expf(l) : 0.f; \
        e = s1r + ps0.z; l = fmaxf(e, 0.2f * e) - CAPV; w2 = (pa0.z > 0) ? __expf(l) : 0.f; \
        e = s1r + ps0.w; l = fmaxf(e, 0.2f * e) - CAPV; w3 = (pa0.w > 0) ? __expf(l) : 0.f; \
        e = s1r + ps1.x; l = fmaxf(e, 0.2f * e) - CAPV; w4 = (pa1.x > 0) ? __expf(l) : 0.f; \
        e = s1r + ps1.y; l = fmaxf(e, 0.2f * e) - CAPV; w5 = (pa1.y > 0) ? __expf(l) : 0.f; \
        e = s1r + ps1.z; l = fmaxf(e, 0.2f * e) - CAPV; w6 = (pa1.z > 0) ? __expf(l) : 0.f; \
        e = s1r + ps1.w; l = fmaxf(e, 0.2f * e) - CAPV; w7 = (pa1.w > 0) ? __expf(l) : 0.f; \
        dn += ((w0 + w1) + (w2 + w3)) + ((w4 + w5) + (w6 + w7));               \
        float4* wp = (float4*)&w_s[buf][r1][jg * 8];                           \
        wp[0] = make_float4(__uint_as_float(tf32r(w0)), __uint_as_float(tf32r(w1)), \
                            __uint_as_float(tf32r(w2)), __uint_as_float(tf32r(w3))); \
        wp[1] = make_float4(__uint_as_float(tf32r(w4)), __uint_as_float(tf32r(w5)), \
                            __uint_as_float(tf32r(w6)), __uint_as_float(tf32r(w7))); \
        *(float4*)&h_s[buf][t >> 4][(t & 15) * 4] = make_float4(               \
            __uint_as_float(tf32r(ph0.x)), __uint_as_float(tf32r(ph0.y)),      \
            __uint_as_float(tf32r(ph0.z)), __uint_as_float(tf32r(ph0.w)));     \
        *(float4*)&h_s[buf][(t + 256) >> 4][((t + 256) & 15) * 4] = make_float4( \
            __uint_as_float(tf32r(ph1.x)), __uint_as_float(tf32r(ph1.y)),      \
            __uint_as_float(tf32r(ph1.z)), __uint_as_float(tf32r(ph1.w)));     \
        *(float4*)&h_s[buf][(t + 512) >> 4][((t + 512) & 15) * 4] = make_float4( \
            __uint_as_float(tf32r(ph2.x)), __uint_as_float(tf32r(ph2.y)),      \
            __uint_as_float(tf32r(ph2.z)), __uint_as_float(tf32r(ph2.w)));     \
        *(float4*)&h_s[buf][(t + 768) >> 4][((t + 768) & 15) * 4] = make_float4( \
            __uint_as_float(tf32r(ph3.x)), __uint_as_float(tf32r(ph3.y)),      \
            __uint_as_float(tf32r(ph3.z)), __uint_as_float(tf32r(ph3.w)));     \
    } while (0)

    FILL_BUF(0);
    __syncthreads();

    int cur = 0;
    for (int j0 = 0; j0 < GN; j0 += JT) {
        const int jn = j0 + JT;
        // ---- prefetch tile t+1 ----
        if (jn < GN) {
            const int j = jn + jg * 8;
            pa0 = *(const int4*)(adjrow + j);
            pa1 = *(const int4*)(adjrow + j + 4);
            ps0 = *(const float4*)(g_s2 + j);
            ps1 = *(const float4*)(g_s2 + j + 4);
            ph0 = *(const float4*)(g_h + (size_t)(jn + (t >> 4)) * GOUT + (t & 15) * 4);
            ph1 = *(const float4*)(g_h + (size_t)(jn + ((t + 256) >> 4)) * GOUT + ((t + 256) & 15) * 4);
            ph2 = *(const float4*)(g_h + (size_t)(jn + ((t + 512) >> 4)) * GOUT + ((t + 512) & 15) * 4);
            ph3 = *(const float4*)(g_h + (size_t)(jn + ((t + 768) >> 4)) * GOUT + ((t + 768) & 15) * 4);
        }

        // ---- phase 2: 8 ksteps x 2 ntiles of m16n8k8 tf32 on buf[cur] ----
#pragma unroll
        for (int ks = 0; ks < 8; ++ks) {
            const unsigned a0 = __float_as_uint(w_s[cur][m * 16 + gid][ks * 8 + tig]);
            const unsigned a1 = __float_as_uint(w_s[cur][m * 16 + gid + 8][ks * 8 + tig]);
            const unsigned a2 = __float_as_uint(w_s[cur][m * 16 + gid][ks * 8 + tig + 4]);
            const unsigned a3 = __float_as_uint(w_s[cur][m * 16 + gid + 8][ks * 8 + tig + 4]);

            const unsigned b00 = __float_as_uint(h_s[cur][ks * 8 + tig][nq * 16 + gid]);
            const unsigned b01 = __float_as_uint(h_s[cur][ks * 8 + tig + 4][nq * 16 + gid]);
            mma_tf32(c00, c01, c02, c03, a0, a1, a2, a3, b00, b01);

            const unsigned b10 = __float_as_uint(h_s[cur][ks * 8 + tig][nq * 16 + 8 + gid]);
            const unsigned b11 = __float_as_uint(h_s[cur][ks * 8 + tig + 4][nq * 16 + 8 + gid]);
            mma_tf32(c10, c11, c12, c13, a0, a1, a2, a3, b10, b11);
        }

        // ---- fill other buffer with prefetched tile ----
        if (jn < GN) {
            FILL_BUF(cur ^ 1);
            __syncthreads();
            cur ^= 1;
        }
    }

    // ---- denominator reduction (deterministic, fp32) ----
    dred[t] = dn;
    __syncthreads();
    if (t < 32) {
        float s = 0.f;
#pragma unroll
        for (int q = 0; q < 8; ++q) s += dred[q * 32 + t];
        denomS[t] = s;
    }
    __syncthreads();

    // ---- epilogue: divide, ELU, store ----
    const int r_lo = m * 16 + gid;
    const int r_hi = r_lo + 8;
    const float inv_lo = 1.f / denomS[r_lo];
    const float inv_hi = 1.f / denomS[r_hi];

    float v;
    float2 o;
    const int colA = nq * 16 + tig * 2;
    const int colB = colA + 8;

    v = c00 * inv_lo; o.x = (v > 0.f) ? v : expm1f(v);
    v = c01 * inv_lo; o.y = (v > 0.f) ? v : expm1f(v);
    *(float2*)(out + (size_t)(row0 + r_lo) * GOUT + colA) = o;
    v = c02 * inv_hi; o.x = (v > 0.f) ? v : expm1f(v);
    v = c03 * inv_hi; o.y = (v > 0.f) ? v : expm1f(v);
    *(float2*)(out + (size_t)(row0 + r_hi) * GOUT + colA) = o;
    v = c10 * inv_lo; o.x = (v > 0.f) ? v : expm1f(v);
    v = c11 * inv_lo; o.y = (v > 0.f) ? v : expm1f(v);
    *(float2*)(out + (size_t)(row0 + r_lo) * GOUT + colB) = o;
    v = c12 * inv_hi; o.x = (v > 0.f) ? v : expm1f(v);
    v = c13 * inv_hi; o.y = (v > 0.f) ? v : expm1f(v);
    *(float2*)(out + (size_t)(row0 + r_hi) * GOUT + colB) = o;
}

// ---------------------------------------------------------------------------
extern "C" void kernel_launch(void* const* d_in, const int* in_sizes, int n_in,
                              void* d_out, int out_size)
{
    const float* X   = (const float*)d_in[0];
    const int*   adj = (const int*)d_in[1];
    const float* W   = (const float*)d_in[2];
    const float* a1  = (const float*)d_in[3];
    const float* a2  = (const float*)d_in[4];
    float* out = (float*)d_out;

    gat_hprime_kernel<<<1024, 256>>>(X, W);
    gat_scores_kernel<<<256, 256>>>(a1, a2);
    gat_attn_kernel<<<256, 256>>>(adj, out);
}